// round 2
// baseline (speedup 1.0000x reference)
#include <cuda_runtime.h>
#include <math.h>

#define D_MODEL   1024
#define NUM_HEADS 16
#define HEAD_DIM  64
#define SEQ       2048
#define BATCH     2
#define M_TOTAL   (BATCH * SEQ)   // 4096 tokens

// ---------------- scratch (allocation-free: __device__ globals) ----------------
__device__ float g_q[(size_t)BATCH * NUM_HEADS * SEQ * HEAD_DIM];     // head-major [bh][s][d]
__device__ float g_k[(size_t)BATCH * NUM_HEADS * SEQ * HEAD_DIM];
__device__ float g_v[(size_t)BATCH * NUM_HEADS * SEQ * HEAD_DIM];
__device__ float g_attn[(size_t)M_TOTAL * D_MODEL];                   // [token][h*64+d]

// ---------------- GEMM: C = X @ W^T + bias ----------------
// X: [M_TOTAL, 1024] row-major, W: [1024, 1024] row-major (torch Linear weight)
// MODE 0: scatter result into head-major scratch [((b*H+h)*SEQ+s)*64 + dd]
// MODE 1: plain row-major out [r*1024 + c]
template <int MODE>
__global__ void __launch_bounds__(256)
gemm_kernel(const float* __restrict__ X, const float* __restrict__ W,
            const float* __restrict__ bias, float* __restrict__ out)
{
    __shared__ float sX[16 * 68];   // [k][m], pad 68 to de-conflict writes
    __shared__ float sW[16 * 68];   // [k][n]

    const int tid = threadIdx.x;
    const int tr  = tid >> 4;        // 0..15 (row group)
    const int tc  = tid & 15;        // 0..15 (col group)
    const int bm  = blockIdx.y * 64;
    const int bn  = blockIdx.x * 64;

    const int lrow = tid >> 2;       // 0..63 (tile row to load)
    const int lc4  = tid & 3;        // 0..3  (float4 index within 16-wide k slab)

    const float* Xp = X + (size_t)(bm + lrow) * D_MODEL + lc4 * 4;
    const float* Wp = W + (size_t)(bn + lrow) * D_MODEL + lc4 * 4;

    float acc[4][4];
#pragma unroll
    for (int i = 0; i < 4; i++)
#pragma unroll
        for (int j = 0; j < 4; j++) acc[i][j] = 0.0f;

    for (int k0 = 0; k0 < D_MODEL; k0 += 16) {
        float4 xv = *reinterpret_cast<const float4*>(Xp + k0);
        float4 wv = *reinterpret_cast<const float4*>(Wp + k0);
        sX[(lc4 * 4 + 0) * 68 + lrow] = xv.x;
        sX[(lc4 * 4 + 1) * 68 + lrow] = xv.y;
        sX[(lc4 * 4 + 2) * 68 + lrow] = xv.z;
        sX[(lc4 * 4 + 3) * 68 + lrow] = xv.w;
        sW[(lc4 * 4 + 0) * 68 + lrow] = wv.x;
        sW[(lc4 * 4 + 1) * 68 + lrow] = wv.y;
        sW[(lc4 * 4 + 2) * 68 + lrow] = wv.z;
        sW[(lc4 * 4 + 3) * 68 + lrow] = wv.w;
        __syncthreads();

#pragma unroll
        for (int k = 0; k < 16; k++) {
            float4 a4 = *reinterpret_cast<const float4*>(&sX[k * 68 + tr * 4]);
            float4 b4 = *reinterpret_cast<const float4*>(&sW[k * 68 + tc * 4]);
            float av[4] = {a4.x, a4.y, a4.z, a4.w};
            float bv[4] = {b4.x, b4.y, b4.z, b4.w};
#pragma unroll
            for (int i = 0; i < 4; i++)
#pragma unroll
                for (int j = 0; j < 4; j++) acc[i][j] += av[i] * bv[j];
        }
        __syncthreads();
    }

#pragma unroll
    for (int i = 0; i < 4; i++) {
        const int r = bm + tr * 4 + i;
#pragma unroll
        for (int j = 0; j < 4; j++) {
            const int c = bn + tc * 4 + j;
            const float v = acc[i][j] + bias[c];
            if (MODE == 0) {
                const int b  = r >> 11;     // token / 2048
                const int s  = r & 2047;
                const int h  = c >> 6;
                const int dd = c & 63;
                out[(((size_t)(b * NUM_HEADS + h) * SEQ + s) << 6) + dd] = v;
            } else {
                out[(size_t)r * D_MODEL + c] = v;
            }
        }
    }
}

// ---------------- Flash attention (fp32, online softmax) ----------------
// grid: (SEQ/64 q-tiles, BATCH*NUM_HEADS), 256 threads.
// smem: exactly 48KB static. P tile aliases the K buffer after S is computed.
__global__ void __launch_bounds__(256)
attn_kernel(const float* __restrict__ Q, const float* __restrict__ K,
            const float* __restrict__ V, float* __restrict__ out)
{
    __shared__ float sQt[64 * 64];   // [d][q]
    __shared__ float sKP[64 * 64];   // Kt [d][k], then Pt [k][q]
    __shared__ float sV [64 * 64];   // [k][d]

    const int bh = blockIdx.y;
    const int q0 = blockIdx.x * 64;
    const float* Qh = Q + (size_t)bh * SEQ * HEAD_DIM;
    const float* Kh = K + (size_t)bh * SEQ * HEAD_DIM;
    const float* Vh = V + (size_t)bh * SEQ * HEAD_DIM;

    const int tid = threadIdx.x;
    const int tr  = tid >> 4;    // 0..15 -> q rows tr*4..tr*4+3
    const int tc  = tid & 15;    // 0..15 -> key/dim cols tc*4..tc*4+3

    // load Q tile transposed: [d][q]
    for (int i = tid; i < 1024; i += 256) {          // 1024 float4s
        const int row = i >> 4;                       // 0..63
        const int c4  = i & 15;                       // 0..15
        float4 v = *reinterpret_cast<const float4*>(&Qh[(size_t)(q0 + row) * 64 + c4 * 4]);
        sQt[(c4 * 4 + 0) * 64 + row] = v.x;
        sQt[(c4 * 4 + 1) * 64 + row] = v.y;
        sQt[(c4 * 4 + 2) * 64 + row] = v.z;
        sQt[(c4 * 4 + 3) * 64 + row] = v.w;
    }

    float m_i[4], l_i[4], o[4][4];
#pragma unroll
    for (int i = 0; i < 4; i++) {
        m_i[i] = -1e30f;
        l_i[i] = 0.0f;
#pragma unroll
        for (int j = 0; j < 4; j++) o[i][j] = 0.0f;
    }
    const float scale = 0.125f;   // 1/sqrt(64)

    for (int kt = 0; kt < SEQ; kt += 64) {
        __syncthreads();   // prev iter done reading sKP/sV; also guards initial Q store

        // load K tile transposed [d][k] and V tile [k][d]
        for (int i = tid; i < 1024; i += 256) {
            const int row = i >> 4;
            const int c4  = i & 15;
            float4 kv = *reinterpret_cast<const float4*>(&Kh[(size_t)(kt + row) * 64 + c4 * 4]);
            sKP[(c4 * 4 + 0) * 64 + row] = kv.x;
            sKP[(c4 * 4 + 1) * 64 + row] = kv.y;
            sKP[(c4 * 4 + 2) * 64 + row] = kv.z;
            sKP[(c4 * 4 + 3) * 64 + row] = kv.w;
            float4 vv = *reinterpret_cast<const float4*>(&Vh[(size_t)(kt + row) * 64 + c4 * 4]);
            *reinterpret_cast<float4*>(&sV[row * 64 + c4 * 4]) = vv;
        }
        __syncthreads();

        // S[q][k] = sum_d Qt[d][q] * Kt[d][k]
        float s[4][4];
#pragma unroll
        for (int i = 0; i < 4; i++)
#pragma unroll
            for (int j = 0; j < 4; j++) s[i][j] = 0.0f;

#pragma unroll 16
        for (int d = 0; d < 64; d++) {
            float4 a4 = *reinterpret_cast<const float4*>(&sQt[d * 64 + tr * 4]);
            float4 b4 = *reinterpret_cast<const float4*>(&sKP[d * 64 + tc * 4]);
            float av[4] = {a4.x, a4.y, a4.z, a4.w};
            float bv[4] = {b4.x, b4.y, b4.z, b4.w};
#pragma unroll
            for (int i = 0; i < 4; i++)
#pragma unroll
                for (int j = 0; j < 4; j++) s[i][j] += av[i] * bv[j];
        }

        // online softmax update (row stats across the 16 tc lanes)
        float alpha[4];
#pragma unroll
        for (int i = 0; i < 4; i++) {
            float mx = -1e30f;
#pragma unroll
            for (int j = 0; j < 4; j++) {
                s[i][j] *= scale;
                mx = fmaxf(mx, s[i][j]);
            }
#pragma unroll
            for (int off = 8; off >= 1; off >>= 1)
                mx = fmaxf(mx, __shfl_xor_sync(0xffffffffu, mx, off));
            const float mnew = fmaxf(m_i[i], mx);
            float rs = 0.0f;
#pragma unroll
            for (int j = 0; j < 4; j++) {
                s[i][j] = __expf(s[i][j] - mnew);
                rs += s[i][j];
            }
#pragma unroll
            for (int off = 8; off >= 1; off >>= 1)
                rs += __shfl_xor_sync(0xffffffffu, rs, off);
            alpha[i] = __expf(m_i[i] - mnew);
            l_i[i]   = l_i[i] * alpha[i] + rs;
            m_i[i]   = mnew;
#pragma unroll
            for (int j = 0; j < 4; j++) o[i][j] *= alpha[i];
        }

        __syncthreads();   // everyone done reading sKP as K

        // write P transposed [k][q] into the K buffer
#pragma unroll
        for (int i = 0; i < 4; i++)
#pragma unroll
            for (int j = 0; j < 4; j++)
                sKP[(tc * 4 + j) * 64 + (tr * 4 + i)] = s[i][j];
        __syncthreads();

        // O[q][dd] += sum_k Pt[k][q] * V[k][dd]
#pragma unroll 16
        for (int k = 0; k < 64; k++) {
            float4 a4 = *reinterpret_cast<const float4*>(&sKP[k * 64 + tr * 4]);
            float4 b4 = *reinterpret_cast<const float4*>(&sV [k * 64 + tc * 4]);
            float av[4] = {a4.x, a4.y, a4.z, a4.w};
            float bv[4] = {b4.x, b4.y, b4.z, b4.w};
#pragma unroll
            for (int i = 0; i < 4; i++)
#pragma unroll
                for (int j = 0; j < 4; j++) o[i][j] += av[i] * bv[j];
        }
    }

    // epilogue: normalize and write [token][h*64+dd]
    const int b = bh >> 4;
    const int h = bh & 15;
#pragma unroll
    for (int i = 0; i < 4; i++) {
        const int srow = q0 + tr * 4 + i;
        const float inv = 1.0f / l_i[i];
#pragma unroll
        for (int j = 0; j < 4; j++) {
            const int c = h * 64 + tc * 4 + j;
            out[(size_t)(b * SEQ + srow) * D_MODEL + c] = o[i][j] * inv;
        }
    }
}

// ---------------- launch ----------------
extern "C" void kernel_launch(void* const* d_in, const int* in_sizes, int n_in,
                              void* d_out, int out_size)
{
    const float* query = (const float*)d_in[0];
    const float* key   = (const float*)d_in[1];
    const float* value = (const float*)d_in[2];
    const float* Wq    = (const float*)d_in[3];
    const float* bq    = (const float*)d_in[4];
    const float* Wk    = (const float*)d_in[5];
    const float* bk    = (const float*)d_in[6];
    const float* Wv    = (const float*)d_in[7];
    const float* bv    = (const float*)d_in[8];
    const float* Wo    = (const float*)d_in[9];
    const float* bo    = (const float*)d_in[10];
    float* out = (float*)d_out;

    // one-time symbol-address lookup (deterministic; keeps the capture call
    // path to pure kernel launches)
    static float *gq = nullptr, *gk = nullptr, *gv = nullptr, *ga = nullptr;
    if (gq == nullptr) {
        cudaGetSymbolAddress((void**)&gq, g_q);
        cudaGetSymbolAddress((void**)&gk, g_k);
        cudaGetSymbolAddress((void**)&gv, g_v);
        cudaGetSymbolAddress((void**)&ga, g_attn);
    }

    dim3 grid_g(D_MODEL / 64, M_TOTAL / 64);   // (16, 64)
    dim3 grid_a(SEQ / 64, BATCH * NUM_HEADS);  // (32, 32)

    gemm_kernel<0><<<grid_g, 256>>>(query, Wq, bq, gq);
    gemm_kernel<0><<<grid_g, 256>>>(key,   Wk, bk, gk);
    gemm_kernel<0><<<grid_g, 256>>>(value, Wv, bv, gv);
    attn_kernel<<<grid_a, 256>>>(gq, gk, gv, ga);
    gemm_kernel<1><<<grid_g, 256>>>(ga, Wo, bo, out);
}

// round 4
// speedup vs baseline: 1.3573x; 1.3573x over previous
#include <cuda_runtime.h>
#include <cuda_bf16.h>
#include <stdint.h>
#include <math.h>

#define D_MODEL   1024
#define NUM_HEADS 16
#define HEAD_DIM  64
#define SEQ       2048
#define BATCH     2
#define M_TOTAL   (BATCH * SEQ)   // 4096 tokens

// ---------------- scratch (allocation-free: __device__ globals) ----------------
__device__ float g_q[(size_t)BATCH * NUM_HEADS * SEQ * HEAD_DIM];     // head-major [bh][s][d]
__device__ float g_k[(size_t)BATCH * NUM_HEADS * SEQ * HEAD_DIM];
__device__ float g_v[(size_t)BATCH * NUM_HEADS * SEQ * HEAD_DIM];
__device__ float g_attn[(size_t)M_TOTAL * D_MODEL];                   // [token][h*64+d]

// ======================= HMMA helpers (plain sm_103-legal) =======================
__device__ __forceinline__ uint32_t smem_u32(const void* p) {
    uint32_t a;
    asm("{ .reg .u64 t; cvta.to.shared.u64 t, %1; cvt.u32.u64 %0, t; }" : "=r"(a) : "l"(p));
    return a;
}
__device__ __forceinline__ void ldsm_x4(uint32_t addr, uint32_t& r0, uint32_t& r1,
                                        uint32_t& r2, uint32_t& r3) {
    asm volatile("ldmatrix.sync.aligned.m8n8.x4.shared.b16 {%0,%1,%2,%3}, [%4];"
                 : "=r"(r0), "=r"(r1), "=r"(r2), "=r"(r3) : "r"(addr));
}
__device__ __forceinline__ void mma16816(float* c, const uint32_t* a, uint32_t b0, uint32_t b1) {
    asm volatile(
        "mma.sync.aligned.m16n8k16.row.col.f32.bf16.bf16.f32 "
        "{%0,%1,%2,%3}, {%4,%5,%6,%7}, {%8,%9}, {%0,%1,%2,%3};"
        : "+f"(c[0]), "+f"(c[1]), "+f"(c[2]), "+f"(c[3])
        : "r"(a[0]), "r"(a[1]), "r"(a[2]), "r"(a[3]), "r"(b0), "r"(b1));
}

// split one float4 into hi (truncated bf16) and lo (bf16 of residual), packed 2x b32 each
__device__ __forceinline__ void split4(const float4& v, uint64_t& hp, uint64_t& lp) {
    uint32_t u0 = __float_as_uint(v.x), u1 = __float_as_uint(v.y);
    uint32_t u2 = __float_as_uint(v.z), u3 = __float_as_uint(v.w);
    uint32_t h01 = __byte_perm(u0, u1, 0x7632);
    uint32_t h23 = __byte_perm(u2, u3, 0x7632);
    float l0 = v.x - __uint_as_float(u0 & 0xFFFF0000u);
    float l1 = v.y - __uint_as_float(u1 & 0xFFFF0000u);
    float l2 = v.z - __uint_as_float(u2 & 0xFFFF0000u);
    float l3 = v.w - __uint_as_float(u3 & 0xFFFF0000u);
    uint32_t lo01, lo23;
    asm("cvt.rn.bf16x2.f32 %0, %1, %2;" : "=r"(lo01) : "f"(l1), "f"(l0));
    asm("cvt.rn.bf16x2.f32 %0, %1, %2;" : "=r"(lo23) : "f"(l3), "f"(l2));
    hp = ((uint64_t)h23 << 32) | h01;
    lp = ((uint64_t)lo23 << 32) | lo01;
}

// ================= HMMA GEMM: C = X @ W^T + bias (bf16 hi/lo x3) =================
// CTA tile 128m x 64n, BK=32, 256 threads (8 warps: 4m x 2n), warp tile 32x32.
// smem rows stride 40 bf16 (80B) -> ldmatrix conflict-free.
// MODE 0: scatter to head-major scratch; MODE 1: row-major out.
#define GS_STRIDE 40   // bf16 elements per row

template <int MODE>
__global__ void __launch_bounds__(256, 2)
gemm_hmma(const float* __restrict__ X, const float* __restrict__ W,
          const float* __restrict__ bias, float* __restrict__ out)
{
    __shared__ __align__(16) uint16_t sXh[128 * GS_STRIDE];
    __shared__ __align__(16) uint16_t sXl[128 * GS_STRIDE];
    __shared__ __align__(16) uint16_t sWh[64 * GS_STRIDE];
    __shared__ __align__(16) uint16_t sWl[64 * GS_STRIDE];

    const int tid = threadIdx.x;
    const int wid = tid >> 5;
    const int lid = tid & 31;
    const int bm  = blockIdx.y * 128;
    const int bn  = blockIdx.x * 64;

    const int warp_m = wid & 3;          // 0..3
    const int warp_n = wid >> 2;         // 0..1
    const int mW = warp_m * 32;
    const int nW = warp_n * 32;

    const uint32_t bXh = smem_u32(sXh), bXl = smem_u32(sXl);
    const uint32_t bWh = smem_u32(sWh), bWl = smem_u32(sWl);

    // loader mapping: row = i*32 + (tid>>3), c4 = tid&7 (float4 within 32-wide k)
    const int lrow = tid >> 3;
    const int lc4  = tid & 7;

    float acc[2][4][4];
#pragma unroll
    for (int a = 0; a < 2; a++)
#pragma unroll
        for (int b = 0; b < 4; b++)
#pragma unroll
            for (int d = 0; d < 4; d++) acc[a][b][d] = 0.0f;

    // ldmatrix per-lane source addresses (byte offsets within tile)
    const int l8  = lid & 7;
    const int lb8 = (lid >> 3) & 1;
    const int lb16 = lid >> 4;
    // A: row = mW + mf*16 + l8 + lb8*8 ; kc = ks*16 + lb16*8
    // B: row = nW + nf16*16 + l8 + lb8*8 ; kc same

    float4 xr[4], wr[2];
#pragma unroll
    for (int i = 0; i < 4; ++i)
        xr[i] = *reinterpret_cast<const float4*>(X + (size_t)(bm + i * 32 + lrow) * D_MODEL + lc4 * 4);
#pragma unroll
    for (int i = 0; i < 2; ++i)
        wr[i] = *reinterpret_cast<const float4*>(W + (size_t)(bn + i * 32 + lrow) * D_MODEL + lc4 * 4);

    for (int c = 0; c < 32; ++c) {
        __syncthreads();   // previous chunk's ldmatrix reads complete
        // convert + store to smem
#pragma unroll
        for (int i = 0; i < 4; ++i) {
            uint64_t hp, lp;
            split4(xr[i], hp, lp);
            const uint32_t off = (uint32_t)((i * 32 + lrow) * GS_STRIDE + lc4 * 4) * 2;
            asm volatile("st.shared.b64 [%0], %1;" :: "r"(bXh + off), "l"(hp) : "memory");
            asm volatile("st.shared.b64 [%0], %1;" :: "r"(bXl + off), "l"(lp) : "memory");
        }
#pragma unroll
        for (int i = 0; i < 2; ++i) {
            uint64_t hp, lp;
            split4(wr[i], hp, lp);
            const uint32_t off = (uint32_t)((i * 32 + lrow) * GS_STRIDE + lc4 * 4) * 2;
            asm volatile("st.shared.b64 [%0], %1;" :: "r"(bWh + off), "l"(hp) : "memory");
            asm volatile("st.shared.b64 [%0], %1;" :: "r"(bWl + off), "l"(lp) : "memory");
        }
        __syncthreads();

        // prefetch next chunk (LDG overlaps MMA below)
        if (c + 1 < 32) {
            const int k0 = (c + 1) * 32;
#pragma unroll
            for (int i = 0; i < 4; ++i)
                xr[i] = *reinterpret_cast<const float4*>(X + (size_t)(bm + i * 32 + lrow) * D_MODEL + k0 + lc4 * 4);
#pragma unroll
            for (int i = 0; i < 2; ++i)
                wr[i] = *reinterpret_cast<const float4*>(W + (size_t)(bn + i * 32 + lrow) * D_MODEL + k0 + lc4 * 4);
        }

#pragma unroll
        for (int ks = 0; ks < 2; ++ks) {
            const int kc = ks * 16 + lb16 * 8;
            uint32_t Ah[2][4], Al[2][4], Bh[2][4], Bl[2][4];
#pragma unroll
            for (int mf = 0; mf < 2; ++mf) {
                const uint32_t ro = (uint32_t)((mW + mf * 16 + l8 + lb8 * 8) * GS_STRIDE + kc) * 2;
                ldsm_x4(bXh + ro, Ah[mf][0], Ah[mf][1], Ah[mf][2], Ah[mf][3]);
                ldsm_x4(bXl + ro, Al[mf][0], Al[mf][1], Al[mf][2], Al[mf][3]);
            }
#pragma unroll
            for (int nf = 0; nf < 2; ++nf) {
                const uint32_t ro = (uint32_t)((nW + nf * 16 + l8 + lb8 * 8) * GS_STRIDE + kc) * 2;
                ldsm_x4(bWh + ro, Bh[nf][0], Bh[nf][1], Bh[nf][2], Bh[nf][3]);
                ldsm_x4(bWl + ro, Bl[nf][0], Bl[nf][1], Bl[nf][2], Bl[nf][3]);
            }
#pragma unroll
            for (int mf = 0; mf < 2; ++mf) {
#pragma unroll
                for (int nf = 0; nf < 2; ++nf) {
#pragma unroll
                    for (int sub = 0; sub < 2; ++sub) {
                        float* cc = acc[mf][nf * 2 + sub];
                        const uint32_t bh0 = Bh[nf][sub], bh1 = Bh[nf][sub + 2];
                        const uint32_t bl0 = Bl[nf][sub], bl1 = Bl[nf][sub + 2];
                        mma16816(cc, Ah[mf], bh0, bh1);
                        mma16816(cc, Ah[mf], bl0, bl1);
                        mma16816(cc, Al[mf], bh0, bh1);
                    }
                }
            }
        }
    }

    // epilogue: fragment c: rows mW+mf*16+(lid>>2)(+8), cols nW+nf8*8+(lid&3)*2
    const int g4 = lid >> 2;
    const int q4 = lid & 3;
#pragma unroll
    for (int mf = 0; mf < 2; ++mf) {
#pragma unroll
        for (int nf8 = 0; nf8 < 4; ++nf8) {
            const int cc = bn + nW + nf8 * 8 + q4 * 2;
            const float bx = bias[cc], by = bias[cc + 1];
#pragma unroll
            for (int half = 0; half < 2; ++half) {
                const int r = bm + mW + mf * 16 + g4 + half * 8;
                float2 v;
                v.x = acc[mf][nf8][half * 2 + 0] + bx;
                v.y = acc[mf][nf8][half * 2 + 1] + by;
                if (MODE == 0) {
                    const int b  = r >> 11;
                    const int s  = r & 2047;
                    const int h  = cc >> 6;
                    const int dd = cc & 63;
                    *reinterpret_cast<float2*>(&out[(((size_t)(b * NUM_HEADS + h) * SEQ + s) << 6) + dd]) = v;
                } else {
                    *reinterpret_cast<float2*>(&out[(size_t)r * D_MODEL + cc]) = v;
                }
            }
        }
    }
}

// ---------------- Flash attention (fp32, online softmax) — unchanged ----------------
__global__ void __launch_bounds__(256)
attn_kernel(const float* __restrict__ Q, const float* __restrict__ K,
            const float* __restrict__ V, float* __restrict__ out)
{
    __shared__ float sQt[64 * 64];   // [d][q]
    __shared__ float sKP[64 * 64];   // Kt [d][k], then Pt [k][q]
    __shared__ float sV [64 * 64];   // [k][d]

    const int bh = blockIdx.y;
    const int q0 = blockIdx.x * 64;
    const float* Qh = Q + (size_t)bh * SEQ * HEAD_DIM;
    const float* Kh = K + (size_t)bh * SEQ * HEAD_DIM;
    const float* Vh = V + (size_t)bh * SEQ * HEAD_DIM;

    const int tid = threadIdx.x;
    const int tr  = tid >> 4;
    const int tc  = tid & 15;

    for (int i = tid; i < 1024; i += 256) {
        const int row = i >> 4;
        const int c4  = i & 15;
        float4 v = *reinterpret_cast<const float4*>(&Qh[(size_t)(q0 + row) * 64 + c4 * 4]);
        sQt[(c4 * 4 + 0) * 64 + row] = v.x;
        sQt[(c4 * 4 + 1) * 64 + row] = v.y;
        sQt[(c4 * 4 + 2) * 64 + row] = v.z;
        sQt[(c4 * 4 + 3) * 64 + row] = v.w;
    }

    float m_i[4], l_i[4], o[4][4];
#pragma unroll
    for (int i = 0; i < 4; i++) {
        m_i[i] = -1e30f;
        l_i[i] = 0.0f;
#pragma unroll
        for (int j = 0; j < 4; j++) o[i][j] = 0.0f;
    }
    const float scale = 0.125f;

    for (int kt = 0; kt < SEQ; kt += 64) {
        __syncthreads();
        for (int i = tid; i < 1024; i += 256) {
            const int row = i >> 4;
            const int c4  = i & 15;
            float4 kv = *reinterpret_cast<const float4*>(&Kh[(size_t)(kt + row) * 64 + c4 * 4]);
            sKP[(c4 * 4 + 0) * 64 + row] = kv.x;
            sKP[(c4 * 4 + 1) * 64 + row] = kv.y;
            sKP[(c4 * 4 + 2) * 64 + row] = kv.z;
            sKP[(c4 * 4 + 3) * 64 + row] = kv.w;
            float4 vv = *reinterpret_cast<const float4*>(&Vh[(size_t)(kt + row) * 64 + c4 * 4]);
            *reinterpret_cast<float4*>(&sV[row * 64 + c4 * 4]) = vv;
        }
        __syncthreads();

        float s[4][4];
#pragma unroll
        for (int i = 0; i < 4; i++)
#pragma unroll
            for (int j = 0; j < 4; j++) s[i][j] = 0.0f;

#pragma unroll 16
        for (int d = 0; d < 64; d++) {
            float4 a4 = *reinterpret_cast<const float4*>(&sQt[d * 64 + tr * 4]);
            float4 b4 = *reinterpret_cast<const float4*>(&sKP[d * 64 + tc * 4]);
            float av[4] = {a4.x, a4.y, a4.z, a4.w};
            float bv[4] = {b4.x, b4.y, b4.z, b4.w};
#pragma unroll
            for (int i = 0; i < 4; i++)
#pragma unroll
                for (int j = 0; j < 4; j++) s[i][j] += av[i] * bv[j];
        }

        float alpha[4];
#pragma unroll
        for (int i = 0; i < 4; i++) {
            float mx = -1e30f;
#pragma unroll
            for (int j = 0; j < 4; j++) {
                s[i][j] *= scale;
                mx = fmaxf(mx, s[i][j]);
            }
#pragma unroll
            for (int off = 8; off >= 1; off >>= 1)
                mx = fmaxf(mx, __shfl_xor_sync(0xffffffffu, mx, off));
            const float mnew = fmaxf(m_i[i], mx);
            float rs = 0.0f;
#pragma unroll
            for (int j = 0; j < 4; j++) {
                s[i][j] = __expf(s[i][j] - mnew);
                rs += s[i][j];
            }
#pragma unroll
            for (int off = 8; off >= 1; off >>= 1)
                rs += __shfl_xor_sync(0xffffffffu, rs, off);
            alpha[i] = __expf(m_i[i] - mnew);
            l_i[i]   = l_i[i] * alpha[i] + rs;
            m_i[i]   = mnew;
#pragma unroll
            for (int j = 0; j < 4; j++) o[i][j] *= alpha[i];
        }

        __syncthreads();
#pragma unroll
        for (int i = 0; i < 4; i++)
#pragma unroll
            for (int j = 0; j < 4; j++)
                sKP[(tc * 4 + j) * 64 + (tr * 4 + i)] = s[i][j];
        __syncthreads();

#pragma unroll 16
        for (int k = 0; k < 64; k++) {
            float4 a4 = *reinterpret_cast<const float4*>(&sKP[k * 64 + tr * 4]);
            float4 b4 = *reinterpret_cast<const float4*>(&sV [k * 64 + tc * 4]);
            float av[4] = {a4.x, a4.y, a4.z, a4.w};
            float bv[4] = {b4.x, b4.y, b4.z, b4.w};
#pragma unroll
            for (int i = 0; i < 4; i++)
#pragma unroll
                for (int j = 0; j < 4; j++) o[i][j] += av[i] * bv[j];
        }
    }

    const int b = bh >> 4;
    const int h = bh & 15;
#pragma unroll
    for (int i = 0; i < 4; i++) {
        const int srow = q0 + tr * 4 + i;
        const float inv = 1.0f / l_i[i];
#pragma unroll
        for (int j = 0; j < 4; j++) {
            const int c = h * 64 + tc * 4 + j;
            out[(size_t)(b * SEQ + srow) * D_MODEL + c] = o[i][j] * inv;
        }
    }
}

// ---------------- launch ----------------
extern "C" void kernel_launch(void* const* d_in, const int* in_sizes, int n_in,
                              void* d_out, int out_size)
{
    const float* query = (const float*)d_in[0];
    const float* key   = (const float*)d_in[1];
    const float* value = (const float*)d_in[2];
    const float* Wq    = (const float*)d_in[3];
    const float* bq    = (const float*)d_in[4];
    const float* Wk    = (const float*)d_in[5];
    const float* bk    = (const float*)d_in[6];
    const float* Wv    = (const float*)d_in[7];
    const float* bv    = (const float*)d_in[8];
    const float* Wo    = (const float*)d_in[9];
    const float* bo    = (const float*)d_in[10];
    float* out = (float*)d_out;

    static float *gq = nullptr, *gk = nullptr, *gv = nullptr, *ga = nullptr;
    if (gq == nullptr) {
        cudaGetSymbolAddress((void**)&gq, g_q);
        cudaGetSymbolAddress((void**)&gk, g_k);
        cudaGetSymbolAddress((void**)&gv, g_v);
        cudaGetSymbolAddress((void**)&ga, g_attn);
    }

    dim3 grid_g(D_MODEL / 64, M_TOTAL / 128);   // (16, 32) = 512 CTAs
    dim3 grid_a(SEQ / 64, BATCH * NUM_HEADS);   // (32, 32)

    gemm_hmma<0><<<grid_g, 256>>>(query, Wq, bq, gq);
    gemm_hmma<0><<<grid_g, 256>>>(key,   Wk, bk, gk);
    gemm_hmma<0><<<grid_g, 256>>>(value, Wv, bv, gv);
    attn_kernel<<<grid_a, 256>>>(gq, gk, gv, ga);
    gemm_hmma<1><<<grid_g, 256>>>(ga, Wo, bo, out);
}